// round 15
// baseline (speedup 1.0000x reference)
#include <cuda_runtime.h>
#include <cuda_fp16.h>
#include <math.h>
#include <stdint.h>

#define PRE    64
#define BATCH  1024
#define NNB    256
#define MASSF  60.0f
#define NBLK   BATCH         // 1024 blocks, one batch each
#define NTHR   256           // 8 nb-lanes x 32 timestep-pairs

// accumulators: [0] = 8(lanes) * 64(den-scale) * sum energy_norm / MASS
//               [1] = sum squared error
__device__ float    g_acc[2] = {0.0f, 0.0f};
__device__ unsigned g_cnt    = 0;

struct __align__(16) NbRec {      // 16B -> one LDS.128
    __half2 mnx2;                 // {-nx, -nx}
    __half2 mny2;                 // {-ny, -ny}
    __half2 ca2;                  // {ca/2, ca/2}
    __half2 sa2;                  // {sa/2, sa/2}
};

// ---------------------------------------------------------------------------
// Fused kernel, 1024 blocks x 256 threads, one batch per block.
// Thread: c = tid&7 (neighbour lane), tg = tid>>3; timesteps {2tg, 2tg+1}
// ride the two half2 lanes end-to-end.
// Per neighbour (= 2 timesteps): 15 fp16 fma-pipe ops + 2 MUFU + 1 LDS.128:
//   dx = px - nx, dy = py - ny                         [2 HADD2]
//   r2e = dx^2 + dy^2 + 2^-20  (eps folded free)       [2]
//   x' = (ca dx + sa dy)/2; x2' = x'^2                 [3]
//   y2' = r2e/4 - x2'                                  [1]
//   den'' = x2'^3 + y2'^3 + 6/64  (= den/64)           [4]
//   w = h2rcp(den'') * h2rsqrt(r2e)  (= 64/(den*r))    [1 mul + 2 MUFU]
//   ex2 += w dx, ey2 += w dy                           [2 HFMA2]
// (vs R13: ds2/m deleted, rcp*rsqrt split; den''-overflow w=0 bias GONE.)
// half2 accumulators flushed to fp32 every 8 neighbours (|w dx| <= 10.7 so
// partials <= ~85; RN noise is zero-mean and averages out over 65536 samples).
// (MASS, the /64 scale, atan2 trig and signs all fold into finalize.)
// ---------------------------------------------------------------------------
__global__ __launch_bounds__(NTHR, 4)
void fused_kernel(const float* __restrict__ out,   // (PRE, BATCH, 2)
                  const float* __restrict__ tgt,   // (PRE, BATCH, 2)
                  const float* __restrict__ nb,    // (BATCH, NNB, 5)
                  float* __restrict__ dst)
{
    __shared__ NbRec s_nb[NNB];
    __shared__ float s_red[16];

    const int tid = threadIdx.x;
    const int b   = blockIdx.x;

    const int c  = tid & 7;           // neighbour lane
    const int tg = tid >> 3;          // timestep pair 0..31

    // ---- point loads early: overlap latency with staging ----
    const float2 pa = ((const float2*)out)[(size_t)(2 * tg)     * BATCH + b];
    const float2 pb = ((const float2*)out)[(size_t)(2 * tg + 1) * BATCH + b];

    // ---- MSE slice (fp32): first 131072 of 262144 global threads ----
    float msum = 0.0f;
    {
        const int g = b * NTHR + tid;
        if (g < PRE * BATCH * 2) {
            const float d = out[g] - tgt[g];
            msum = d * d;
        }
    }

    // ---- stage neighbours: one per thread; sincos fp32, /2 fold ----
    {
        const float* q = nb + ((size_t)b * NNB + tid) * 5;
        const float nx = q[0];
        const float ny = q[1];
        const float an = q[4];
        float sa, ca;
        __sincosf(an, &sa, &ca);
        NbRec rec;
        rec.mnx2 = __float2half2_rn(-nx);
        rec.mny2 = __float2half2_rn(-ny);
        rec.ca2  = __float2half2_rn(ca * 0.5f);
        rec.sa2  = __float2half2_rn(sa * 0.5f);
        s_nb[tid] = rec;
    }
    __syncthreads();

    // positions packed to half2 ONCE (two timesteps in the two lanes)
    const __half2 px2 = __floats2half2_rn(pa.x, pb.x);
    const __half2 py2 = __floats2half2_rn(pa.y, pb.y);

    const __half2 c025 = __float2half2_rn(0.25f);
    const __half2 cden = __float2half2_rn(0.09375f);        // 6/64
    const __half2 epsm = __float2half2_rn(9.5367432e-7f);   // 2^-20 (subnormal)
    const __half2 hzero = __float2half2_rn(0.0f);

    float exa = 0.0f, eya = 0.0f;     // fp32 master accumulators
    float exb = 0.0f, eyb = 0.0f;

    #pragma unroll
    for (int o = 0; o < 4; ++o) {                 // 4 outer flush groups
        __half2 exh = hzero;
        __half2 eyh = hzero;

        #pragma unroll
        for (int j = 0; j < 8; ++j) {             // 8 neighbours per group
            const NbRec nr = s_nb[(((o << 3) | j) << 3) | c];

            // fp16 deltas
            const __half2 dx2 = __hadd2(px2, nr.mnx2);
            const __half2 dy2 = __hadd2(py2, nr.mny2);

            // r2 + eps in one chain (eps guards exact-collision NaN for free)
            const __half2 r2e = __hfma2(dx2, dx2, __hfma2(dy2, dy2, epsm));

            // rotated x and the den/64 polynomial
            const __half2 x_  = __hfma2(nr.ca2, dx2, __hmul2(nr.sa2, dy2)); // x/2
            const __half2 x2  = __hmul2(x_, x_);                            // x^2/4
            const __half2 y2  = __hfma2(r2e, c025, __hneg2(x2));            // y^2/4
            const __half2 x4  = __hmul2(x2, x2);
            const __half2 y4  = __hmul2(y2, y2);
            const __half2 den = __hfma2(x4, x2, __hfma2(y4, y2, cden));     // den/64

            // w = (64/den) * (1/r)  via rcp * rsqrt (2 MUFU, no overflow cutoff)
            const __half2 w2 = __hmul2(h2rcp(den), h2rsqrt(r2e));

            // fp16 accumulation (flushed every 8 iters)
            exh = __hfma2(w2, dx2, exh);
            eyh = __hfma2(w2, dy2, eyh);
        }

        // flush half2 partials to fp32
        exa += __low2float(exh);  exb += __high2float(exh);
        eya += __low2float(eyh);  eyb += __high2float(eyh);
    }

    // reduce partial sums over the 8 c-lanes (bits [0:3) of lane id)
    #pragma unroll
    for (int o = 1; o <= 4; o <<= 1) {
        exa += __shfl_xor_sync(0xffffffffu, exa, o);
        eya += __shfl_xor_sync(0xffffffffu, eya, o);
        exb += __shfl_xor_sync(0xffffffffu, exb, o);
        eyb += __shfl_xor_sync(0xffffffffu, eyb, o);
    }

    // identical on 8 c-lanes -> warp sum overcounts 8x (folded in finalize)
    float v = sqrtf(fmaf(exa, exa, eya * eya))
            + sqrtf(fmaf(exb, exb, eyb * eyb));

    #pragma unroll
    for (int o = 16; o; o >>= 1) {
        v    += __shfl_xor_sync(0xffffffffu, v,    o);
        msum += __shfl_xor_sync(0xffffffffu, msum, o);
    }
    if ((tid & 31) == 0) {
        s_red[(tid >> 5) * 2 + 0] = v;
        s_red[(tid >> 5) * 2 + 1] = msum;
    }
    __syncthreads();

    if (tid == 0) {
        float fv = 0.0f, fm = 0.0f;
        #pragma unroll
        for (int w8 = 0; w8 < 8; ++w8) {
            fv += s_red[w8 * 2 + 0];
            fm += s_red[w8 * 2 + 1];
        }
        atomicAdd(&g_acc[0], fv);
        atomicAdd(&g_acc[1], fm);
        __threadfence();
        const unsigned rr = atomicAdd(&g_cnt, 1u);
        if (rr == (unsigned)(NBLK - 1)) {
            __threadfence();
            const float fe = *((volatile float*)&g_acc[0]);
            const float mm = *((volatile float*)&g_acc[1]);
            // fe = 8(lanes) * 64(w-scale: w = 64/(den r)) * sum(v)/MASS
            dst[0] = mm * (1.0f / (float)(PRE * BATCH * 2))
                   + fe * (MASSF / (512.0f * (float)(PRE * BATCH)));
            g_acc[0] = 0.0f;
            g_acc[1] = 0.0f;
            __threadfence();
            g_cnt = 0;
        }
    }
}

extern "C" void kernel_launch(void* const* d_in, const int* in_sizes, int n_in,
                              void* d_out, int out_size)
{
    const float* output     = (const float*)d_in[0];   // (64, 1024, 2)
    const float* target     = (const float*)d_in[1];   // (64, 1024, 2)
    const float* neighbours = (const float*)d_in[2];   // (1024, 256, 5)
    float* dst = (float*)d_out;

    fused_kernel<<<NBLK, NTHR>>>(output, target, neighbours, dst);
}

// round 16
// speedup vs baseline: 1.0849x; 1.0849x over previous
#include <cuda_runtime.h>
#include <cuda_fp16.h>
#include <math.h>
#include <stdint.h>

#define PRE    64
#define BATCH  1024
#define NNB    256
#define MASSF  60.0f
#define NBLK   BATCH         // 1024 blocks, one batch each
#define NTHR   256           // 8 nb-lanes x 32 timestep-pairs

// accumulators: [0] = 8(lanes) * 64(den-scale) * sum energy_norm / MASS
//               [1] = sum squared error
__device__ float    g_acc[2] = {0.0f, 0.0f};
__device__ unsigned g_cnt    = 0;

struct __align__(16) NbRec {      // 16B -> one LDS.128
    __half2 mnx2;                 // {-nx, -nx}
    __half2 mny2;                 // {-ny, -ny}
    __half2 ca2;                  // {ca/2, ca/2}
    __half2 sa2;                  // {sa/2, sa/2}
};

// ---------------------------------------------------------------------------
// Fused kernel, 1024 blocks x 256 threads, one batch per block.
// Thread: c = tid&7 (neighbour lane), tg = tid>>3; timesteps {2tg, 2tg+1}
// ride the two half2 lanes end-to-end.
// Per neighbour (= 2 timesteps): 16 fp16 fma-pipe ops + 1 MUFU + 1 LDS.128
// (R13 math — single h2rsqrt, proven 96%-of-ceiling —
//  + R15's 4 flush groups, amortized flush 2 -> 1 op/iter):
//   dx = px - nx, dy = py - ny                         [2 HADD2]
//   r2 = dx^2 + dy^2                                   [2]
//   x' = (ca dx + sa dy)/2; x2' = x'^2                 [3]
//   y2' = r2/4 - x2'                                   [1]
//   den'' = x2'^3 + y2'^3 + 6/64  (= den/64)           [4]
//   m = den''^2 r2 + 2^-20; w = h2rsqrt(m)             [2 + 1 MUFU]
//   ex2 += w dx, ey2 += w dy                           [2 HFMA2]
// half2 accumulators flushed to fp32 every 8 neighbours (validated in R15:
// rel_err stayed far under threshold; noise is zero-mean over 65536 samples).
// den''^2 overflow (den>16377, P~4e-4) -> w=0, bias ~6e-6; eps=2^-20 only
// guards exact r2=0 -> NaN.
// (MASS, the /64 scale, atan2 trig and signs all fold into finalize.)
// ---------------------------------------------------------------------------
__global__ __launch_bounds__(NTHR, 4)
void fused_kernel(const float* __restrict__ out,   // (PRE, BATCH, 2)
                  const float* __restrict__ tgt,   // (PRE, BATCH, 2)
                  const float* __restrict__ nb,    // (BATCH, NNB, 5)
                  float* __restrict__ dst)
{
    __shared__ NbRec s_nb[NNB];
    __shared__ float s_red[16];

    const int tid = threadIdx.x;
    const int b   = blockIdx.x;

    const int c  = tid & 7;           // neighbour lane
    const int tg = tid >> 3;          // timestep pair 0..31

    // ---- point loads early: overlap latency with staging ----
    const float2 pa = ((const float2*)out)[(size_t)(2 * tg)     * BATCH + b];
    const float2 pb = ((const float2*)out)[(size_t)(2 * tg + 1) * BATCH + b];

    // ---- MSE slice (fp32): first 131072 of 262144 global threads ----
    float msum = 0.0f;
    {
        const int g = b * NTHR + tid;
        if (g < PRE * BATCH * 2) {
            const float d = out[g] - tgt[g];
            msum = d * d;
        }
    }

    // ---- stage neighbours: one per thread; sincos fp32, /2 fold ----
    {
        const float* q = nb + ((size_t)b * NNB + tid) * 5;
        const float nx = q[0];
        const float ny = q[1];
        const float an = q[4];
        float sa, ca;
        __sincosf(an, &sa, &ca);
        NbRec rec;
        rec.mnx2 = __float2half2_rn(-nx);
        rec.mny2 = __float2half2_rn(-ny);
        rec.ca2  = __float2half2_rn(ca * 0.5f);
        rec.sa2  = __float2half2_rn(sa * 0.5f);
        s_nb[tid] = rec;
    }
    __syncthreads();

    // positions packed to half2 ONCE (two timesteps in the two lanes)
    const __half2 px2 = __floats2half2_rn(pa.x, pb.x);
    const __half2 py2 = __floats2half2_rn(pa.y, pb.y);

    const __half2 c025 = __float2half2_rn(0.25f);
    const __half2 cden = __float2half2_rn(0.09375f);        // 6/64
    const __half2 epsm = __float2half2_rn(9.5367432e-7f);   // 2^-20 (subnormal)
    const __half2 hzero = __float2half2_rn(0.0f);

    float exa = 0.0f, eya = 0.0f;     // fp32 master accumulators
    float exb = 0.0f, eyb = 0.0f;

    #pragma unroll
    for (int o = 0; o < 4; ++o) {                 // 4 outer flush groups
        __half2 exh = hzero;
        __half2 eyh = hzero;

        #pragma unroll
        for (int j = 0; j < 8; ++j) {             // 8 neighbours per group
            const NbRec nr = s_nb[(((o << 3) | j) << 3) | c];

            // fp16 deltas
            const __half2 dx2 = __hadd2(px2, nr.mnx2);
            const __half2 dy2 = __hadd2(py2, nr.mny2);

            // fp16 polynomial, timesteps in the two half2 lanes
            const __half2 r2  = __hfma2(dx2, dx2, __hmul2(dy2, dy2));
            const __half2 x_  = __hfma2(nr.ca2, dx2, __hmul2(nr.sa2, dy2)); // x/2
            const __half2 x2  = __hmul2(x_, x_);                            // x^2/4
            const __half2 y2  = __hfma2(r2, c025, __hneg2(x2));             // y^2/4
            const __half2 x4  = __hmul2(x2, x2);
            const __half2 y4  = __hmul2(y2, y2);
            const __half2 den = __hfma2(x4, x2, __hfma2(y4, y2, cden));     // den/64
            const __half2 ds2 = __hmul2(den, den);
            const __half2 m   = __hfma2(ds2, r2, epsm);
            const __half2 w2  = h2rsqrt(m);                                 // 64/(den*r)

            // fp16 accumulation (flushed every 8 iters)
            exh = __hfma2(w2, dx2, exh);
            eyh = __hfma2(w2, dy2, eyh);
        }

        // flush half2 partials to fp32
        exa += __low2float(exh);  exb += __high2float(exh);
        eya += __low2float(eyh);  eyb += __high2float(eyh);
    }

    // reduce partial sums over the 8 c-lanes (bits [0:3) of lane id)
    #pragma unroll
    for (int o = 1; o <= 4; o <<= 1) {
        exa += __shfl_xor_sync(0xffffffffu, exa, o);
        eya += __shfl_xor_sync(0xffffffffu, eya, o);
        exb += __shfl_xor_sync(0xffffffffu, exb, o);
        eyb += __shfl_xor_sync(0xffffffffu, eyb, o);
    }

    // identical on 8 c-lanes -> warp sum overcounts 8x (folded in finalize)
    float v = sqrtf(fmaf(exa, exa, eya * eya))
            + sqrtf(fmaf(exb, exb, eyb * eyb));

    #pragma unroll
    for (int o = 16; o; o >>= 1) {
        v    += __shfl_xor_sync(0xffffffffu, v,    o);
        msum += __shfl_xor_sync(0xffffffffu, msum, o);
    }
    if ((tid & 31) == 0) {
        s_red[(tid >> 5) * 2 + 0] = v;
        s_red[(tid >> 5) * 2 + 1] = msum;
    }
    __syncthreads();

    if (tid == 0) {
        float fv = 0.0f, fm = 0.0f;
        #pragma unroll
        for (int w8 = 0; w8 < 8; ++w8) {
            fv += s_red[w8 * 2 + 0];
            fm += s_red[w8 * 2 + 1];
        }
        atomicAdd(&g_acc[0], fv);
        atomicAdd(&g_acc[1], fm);
        __threadfence();
        const unsigned rr = atomicAdd(&g_cnt, 1u);
        if (rr == (unsigned)(NBLK - 1)) {
            __threadfence();
            const float fe = *((volatile float*)&g_acc[0]);
            const float mm = *((volatile float*)&g_acc[1]);
            // fe = 8(lanes) * 64(w-scale: w = 64/(den r)) * sum(v)/MASS
            dst[0] = mm * (1.0f / (float)(PRE * BATCH * 2))
                   + fe * (MASSF / (512.0f * (float)(PRE * BATCH)));
            g_acc[0] = 0.0f;
            g_acc[1] = 0.0f;
            __threadfence();
            g_cnt = 0;
        }
    }
}

extern "C" void kernel_launch(void* const* d_in, const int* in_sizes, int n_in,
                              void* d_out, int out_size)
{
    const float* output     = (const float*)d_in[0];   // (64, 1024, 2)
    const float* target     = (const float*)d_in[1];   // (64, 1024, 2)
    const float* neighbours = (const float*)d_in[2];   // (1024, 256, 5)
    float* dst = (float*)d_out;

    fused_kernel<<<NBLK, NTHR>>>(output, target, neighbours, dst);
}